// round 1
// baseline (speedup 1.0000x reference)
#include <cuda_runtime.h>

#define BATCH 16
#define CH    128
#define HGT   128
#define WID   128

#define TW    32      // spatial tile width
#define TH    8       // spatial tile height
#define CO_T  32      // output channels per block
#define CC    8       // input channels per smem chunk
#define NTHREADS 256

#define IN_ROW_STRIDE 37            // (TW+2)=34 padded to 37 -> bank-conflict-free
#define IN_TILE_ROWS  (TH + 2)      // 10

// Scratch (static device globals; no runtime allocation allowed)
__device__ float g_x[(size_t)BATCH * CH * HGT * WID];
__device__ float g_t[(size_t)BATCH * CH * HGT * WID];

// MODE 0: out = relu(conv(in,w)+bias)
// MODE 1: out = xadd + (1/3)*(conv(in,w)+bias)
// MODE 2: out = relu(xadd + (1/3)*(conv(in,w)+bias))
template <int MODE>
__global__ __launch_bounds__(NTHREADS)
void conv3x3_kernel(const float* __restrict__ in,
                    const float* __restrict__ wgt,
                    const float* __restrict__ bias,
                    const float* __restrict__ xadd,
                    float* __restrict__ out)
{
    __shared__ float in_s[CC * IN_TILE_ROWS * IN_ROW_STRIDE];
    __shared__ float w_s[CO_T * CC * 9];

    const int tid = threadIdx.x;
    const int tx  = tid & 63;   // pixel group 0..63
    const int ty  = tid >> 6;   // channel group 0..3 (uniform per warp -> weight broadcast)

    const int w0      = blockIdx.x * TW;
    const int h0      = blockIdx.y * TH;
    const int co_base = (blockIdx.z & 3) * CO_T;
    const int b       = blockIdx.z >> 2;

    const int ph = tx >> 3;          // output row within tile 0..7
    const int pw = (tx & 7) * 4;     // output col base within tile 0,4,...,28

    float acc[8][4];
#pragma unroll
    for (int c = 0; c < 8; c++)
#pragma unroll
        for (int p = 0; p < 4; p++) acc[c][p] = 0.f;

    const float* in_b = in + (size_t)b * CH * HGT * WID;

    for (int c0 = 0; c0 < CH; c0 += CC) {
        __syncthreads();
        // --- load input tile (CC x 10 x 34, zero-padded halo) ---
        for (int i = tid; i < CC * IN_TILE_ROWS * 34; i += NTHREADS) {
            int ci  = i / (IN_TILE_ROWS * 34);
            int rem = i - ci * (IN_TILE_ROWS * 34);
            int r   = rem / 34;
            int col = rem - r * 34;
            int gh = h0 + r - 1;
            int gw = w0 + col - 1;
            float v = 0.f;
            if ((unsigned)gh < HGT && (unsigned)gw < WID)
                v = in_b[((c0 + ci) * HGT + gh) * WID + gw];
            in_s[ci * (IN_TILE_ROWS * IN_ROW_STRIDE) + r * IN_ROW_STRIDE + col] = v;
        }
        // --- load weights: 72 contiguous floats per output channel ---
        for (int i = tid; i < CO_T * CC * 9; i += NTHREADS) {
            int co  = i / (CC * 9);
            int rem = i - co * (CC * 9);
            w_s[i] = wgt[(size_t)(co_base + co) * (CH * 9) + c0 * 9 + rem];
        }
        __syncthreads();

        // --- compute ---
#pragma unroll
        for (int ci = 0; ci < CC; ci++) {
            const float* in_ci = &in_s[ci * (IN_TILE_ROWS * IN_ROW_STRIDE)];
#pragma unroll
            for (int kh = 0; kh < 3; kh++) {
                float row[6];
                const float* rp = &in_ci[(ph + kh) * IN_ROW_STRIDE + pw];
#pragma unroll
                for (int j = 0; j < 6; j++) row[j] = rp[j];
#pragma unroll
                for (int kw = 0; kw < 3; kw++) {
#pragma unroll
                    for (int c = 0; c < 8; c++) {
                        float wv = w_s[(ty * 8 + c) * 72 + ci * 9 + kh * 3 + kw];
#pragma unroll
                        for (int p = 0; p < 4; p++)
                            acc[c][p] += wv * row[kw + p];
                    }
                }
            }
        }
    }

    // --- epilogue ---
#pragma unroll
    for (int c = 0; c < 8; c++) {
        int co = co_base + ty * 8 + c;
        float bv = bias[co];
        size_t base = (((size_t)b * CH + co) * HGT + (h0 + ph)) * WID + (w0 + pw);
#pragma unroll
        for (int p = 0; p < 4; p++) {
            float v = acc[c][p] + bv;
            if (MODE == 0) {
                v = fmaxf(v, 0.f);
            } else {
                v = xadd[base + p] + (1.0f / 3.0f) * v;
                if (MODE == 2) v = fmaxf(v, 0.f);
            }
            out[base + p] = v;
        }
    }
}

extern "C" void kernel_launch(void* const* d_in, const int* in_sizes, int n_in,
                              void* d_out, int out_size)
{
    const float* x  = (const float*)d_in[0];
    const float* w1 = (const float*)d_in[1];
    const float* b1 = (const float*)d_in[2];
    const float* w2 = (const float*)d_in[3];
    const float* b2 = (const float*)d_in[4];
    float* out = (float*)d_out;

    float *gx, *gt;
    cudaGetSymbolAddress((void**)&gx, g_x);
    cudaGetSymbolAddress((void**)&gt, g_t);

    dim3 grid(WID / TW, HGT / TH, BATCH * 4);
    dim3 blk(NTHREADS);

    // step 1: t = relu(conv1(x)+b1); x1 = x + h*(conv2(t)+b2)
    conv3x3_kernel<0><<<grid, blk>>>(x,  w1, b1, nullptr, gt);
    conv3x3_kernel<1><<<grid, blk>>>(gt, w2, b2, x,       gx);
    // step 2 (in-place x update: epilogue is elementwise in xadd)
    conv3x3_kernel<0><<<grid, blk>>>(gx, w1, b1, nullptr, gt);
    conv3x3_kernel<1><<<grid, blk>>>(gt, w2, b2, gx,      gx);
    // step 3: final relu fused
    conv3x3_kernel<0><<<grid, blk>>>(gx, w1, b1, nullptr, gt);
    conv3x3_kernel<2><<<grid, blk>>>(gt, w2, b2, gx,      out);
}

// round 3
// speedup vs baseline: 3.7504x; 3.7504x over previous
#include <cuda_runtime.h>
#include <cstdint>

#define BATCH 16
#define CH    128
#define HGT   128
#define WID   128
#define NTHR  256

#define NSTAGE   12
#define ASLICE_F 4608          // 128co * 36 floats per kw slice
#define A_BYTES  55296         // 3 * ASLICE_F * 4
#define B_OFF_B  55296
#define B_OFF_F  13824
#define BROW_F   136           // padded row stride (floats)
#define B_BYTES  17408         // 32 * 136 * 4
#define SLOT_B   72704
#define SLOT_F   18176
#define SMEM_DYN (2*SLOT_B)    // 145408 B

__device__ float g_x [(size_t)BATCH*CH*HGT*WID];   // fp32 state
__device__ float g_xr[(size_t)BATCH*CH*HGT*WID];   // tf32-rounded conv input
__device__ float g_t [(size_t)BATCH*CH*HGT*WID];   // rounded t
__device__ float g_wp[2*9*128*128];                // packed tf32 weights

// ---------- helpers ----------
__device__ __forceinline__ uint32_t smem_u32(const void* p){
    uint32_t a; asm("{ .reg .u64 t; cvta.to.shared.u64 t, %1; cvt.u32.u64 %0, t; }":"=r"(a):"l"(p));
    return a;
}
__device__ __forceinline__ float f2tf32(float f){
    uint32_t r; asm("cvt.rna.tf32.f32 %0, %1;":"=r"(r):"f"(f));
    return __uint_as_float(r);
}
__device__ __forceinline__ void cp16(uint32_t dst, const void* src, uint32_t ss){
    asm volatile("cp.async.cg.shared.global [%0], [%1], 16, %2;"
                 :: "r"(dst), "l"(src), "r"(ss) : "memory");
}
#define CP_COMMIT() asm volatile("cp.async.commit_group;":::"memory")
template<int N> __device__ __forceinline__ void cp_wait(){
    asm volatile("cp.async.wait_group %0;"::"n"(N):"memory");
}
__device__ __forceinline__ void mma8(float* d, const uint32_t* a, uint32_t b0, uint32_t b1){
    asm volatile("mma.sync.aligned.m16n8k8.row.col.f32.tf32.tf32.f32 "
        "{%0,%1,%2,%3}, {%4,%5,%6,%7}, {%8,%9}, {%0,%1,%2,%3};"
        : "+f"(d[0]), "+f"(d[1]), "+f"(d[2]), "+f"(d[3])
        : "r"(a[0]), "r"(a[1]), "r"(a[2]), "r"(a[3]), "r"(b0), "r"(b1));
}

// ---------- weight pack (tf32-rounded, [s=kh*4+chunk][kw][co][ci32]) ----------
__global__ void pack_w(const float* __restrict__ w1, const float* __restrict__ w2,
                       float* __restrict__ dst){
    int idx = blockIdx.x*blockDim.x + threadIdx.x;
    if (idx >= 2*128*128*9) return;
    int set = idx / (128*128*9);
    int r   = idx % (128*128*9);
    int co = r / (128*9);
    int r2 = r % (128*9);
    int ci = r2 / 9, k9 = r2 % 9;
    int kh = k9/3, kw = k9%3, chunk = ci>>5, cl = ci&31;
    const float* w = set ? w2 : w1;
    dst[(size_t)set*147456 + (((size_t)(kh*4+chunk)*3 + kw)*128 + co)*32 + cl] = f2tf32(w[r]);
}

// ---------- round pre-pass ----------
__global__ void round_x(const float4* __restrict__ in, float4* __restrict__ out, int n4){
    for (int i = blockIdx.x*blockDim.x + threadIdx.x; i < n4; i += gridDim.x*blockDim.x){
        float4 v = in[i];
        v.x = f2tf32(v.x); v.y = f2tf32(v.y); v.z = f2tf32(v.z); v.w = f2tf32(v.w);
        out[i] = v;
    }
}

// ---------- conv kernel ----------
// MODE 0: out = rna(relu(conv+b))
// MODE 1: v = xadd + (conv+b)/3 ; out = v ; out2 = rna(v)
// MODE 2: out = relu(xadd + (conv+b)/3)
template<int MODE>
__global__ void __launch_bounds__(NTHR, 1)
conv_mma(const float* __restrict__ in, const float* __restrict__ wp,
         const float* __restrict__ bias, const float* __restrict__ xadd,
         float* __restrict__ out, float* __restrict__ out2)
{
    extern __shared__ __align__(1024) float sm[];
    const int tid = threadIdx.x, lane = tid&31, wid = tid>>5;
    const int g = lane>>2, t = lane&3;
    const int wm = wid&3, wn = wid>>2;
    const int h0 = blockIdx.x, b = blockIdx.y;
    const float* in_b = in + (size_t)b*CH*HGT*WID;

    float d[2][8][4];
#pragma unroll
    for (int mt=0;mt<2;mt++)
#pragma unroll
        for (int nt=0;nt<8;nt++)
#pragma unroll
            for (int c=0;c<4;c++) d[mt][nt][c] = 0.f;

    // ---- stage issue: cp.async A (weights) + B (one padded input row) ----
    auto issue_stage = [&](int s, int slot){
        float* sl = sm + slot*SLOT_F;
        uint32_t base = smem_u32(sl);
        // A: 3072 x 16B chunks, contiguous source
        const float4* asrc = (const float4*)(wp + (size_t)s*12288);
#pragma unroll
        for (int i=0;i<12;i++){
            int u = tid + i*256;
            int kw = u>>10, rem = u&1023;
            int co = rem>>3, kgrp = rem&7;
            cp16(base + kw*18432 + co*144 + kgrp*16, asrc + u, 16);
        }
        // B: 32 ci rows x 32 chunks; zero-fill if row out of image
        int kh = s>>2, chunk = s&3;
        int r_in = h0 + kh - 1;
        uint32_t ss = ((unsigned)r_in < HGT) ? 16u : 0u;
        int r_clamp = ((unsigned)r_in < HGT) ? r_in : 0;
        const float* bsrc = in_b + ((size_t)(chunk*32)*HGT + r_clamp)*WID;
#pragma unroll
        for (int i=0;i<4;i++){
            int v = tid + i*256;
            int ci = v>>5, cw = v&31;
            cp16(base + B_OFF_B + ci*544 + 16 + cw*16,
                 bsrc + (size_t)ci*HGT*WID + cw*4, ss);
        }
        // halo edge floats (w=-1 at float idx 3, w=128 at idx 132): always zero
        if (tid < 64){
            int ci = tid>>1;
            int e  = (tid&1) ? 528 : 12;
            *(float*)((char*)sl + B_OFF_B + ci*544 + e) = 0.f;
        }
    };

    issue_stage(0, 0);
    CP_COMMIT();

    for (int s=0; s<NSTAGE; s++){
        if (s < NSTAGE-1){ issue_stage(s+1, (s+1)&1); CP_COMMIT(); cp_wait<1>(); }
        else             { cp_wait<0>(); }
        __syncthreads();

        const float* A = sm + (s&1)*SLOT_F;
        const float* B = A + B_OFF_F;
#pragma unroll
        for (int kw=0; kw<3; kw++){
#pragma unroll
            for (int k8=0; k8<4; k8++){
                const int col = k8*8 + t;
                uint32_t a[2][4];
#pragma unroll
                for (int mt=0; mt<2; mt++){
                    const float* ap = A + kw*ASLICE_F + (wm*32 + mt*16 + g)*36 + col;
                    a[mt][0] = __float_as_uint(ap[0]);
                    a[mt][1] = __float_as_uint(ap[288]);   // +8 rows
                    a[mt][2] = __float_as_uint(ap[4]);     // +4 cols
                    a[mt][3] = __float_as_uint(ap[292]);
                }
                const float* bp = B + col*BROW_F + 3 + wn*64 + g + kw;
#pragma unroll
                for (int nt=0; nt<8; nt++){
                    uint32_t b0 = __float_as_uint(bp[nt*8]);
                    uint32_t b1 = __float_as_uint(bp[nt*8 + 544]);  // k+4 rows
                    mma8(d[0][nt], a[0], b0, b1);
                    mma8(d[1][nt], a[1], b0, b1);
                }
            }
        }
        __syncthreads();
    }

    // ---- epilogue ----
    const float inv3 = 1.0f/3.0f;
#pragma unroll
    for (int mt=0; mt<2; mt++){
        const int co0 = wm*32 + mt*16 + g;
        const int co1 = co0 + 8;
        const float bv0 = bias[co0], bv1 = bias[co1];
        float* o0 = out + (((size_t)b*CH + co0)*HGT + h0)*WID;
        float* o1 = out + (((size_t)b*CH + co1)*HGT + h0)*WID;
        const float* x0 = (MODE!=0) ? xadd + (((size_t)b*CH + co0)*HGT + h0)*WID : nullptr;
        const float* x1 = (MODE!=0) ? xadd + (((size_t)b*CH + co1)*HGT + h0)*WID : nullptr;
        float* r0 = (MODE==1) ? out2 + (((size_t)b*CH + co0)*HGT + h0)*WID : nullptr;
        float* r1 = (MODE==1) ? out2 + (((size_t)b*CH + co1)*HGT + h0)*WID : nullptr;
#pragma unroll
        for (int nt=0; nt<8; nt++){
            const int n = wn*64 + nt*8 + t*2;
            float v00 = d[mt][nt][0] + bv0, v01 = d[mt][nt][1] + bv0;
            float v10 = d[mt][nt][2] + bv1, v11 = d[mt][nt][3] + bv1;
            if (MODE == 0){
                v00 = f2tf32(fmaxf(v00, 0.f)); v01 = f2tf32(fmaxf(v01, 0.f));
                v10 = f2tf32(fmaxf(v10, 0.f)); v11 = f2tf32(fmaxf(v11, 0.f));
                *(float2*)(o0 + n) = make_float2(v00, v01);
                *(float2*)(o1 + n) = make_float2(v10, v11);
            } else {
                float2 xa = *(const float2*)(x0 + n);
                float2 xb = *(const float2*)(x1 + n);
                v00 = xa.x + inv3*v00; v01 = xa.y + inv3*v01;
                v10 = xb.x + inv3*v10; v11 = xb.y + inv3*v11;
                if (MODE == 2){
                    v00 = fmaxf(v00,0.f); v01 = fmaxf(v01,0.f);
                    v10 = fmaxf(v10,0.f); v11 = fmaxf(v11,0.f);
                }
                *(float2*)(o0 + n) = make_float2(v00, v01);
                *(float2*)(o1 + n) = make_float2(v10, v11);
                if (MODE == 1){
                    *(float2*)(r0 + n) = make_float2(f2tf32(v00), f2tf32(v01));
                    *(float2*)(r1 + n) = make_float2(f2tf32(v10), f2tf32(v11));
                }
            }
        }
    }
}

// ---------- launch ----------
extern "C" void kernel_launch(void* const* d_in, const int* in_sizes, int n_in,
                              void* d_out, int out_size)
{
    const float* x  = (const float*)d_in[0];
    const float* w1 = (const float*)d_in[1];
    const float* b1 = (const float*)d_in[2];
    const float* w2 = (const float*)d_in[3];
    const float* b2 = (const float*)d_in[4];
    float* out = (float*)d_out;

    float *gx, *gxr, *gt, *gwp;
    cudaGetSymbolAddress((void**)&gx,  g_x);
    cudaGetSymbolAddress((void**)&gxr, g_xr);
    cudaGetSymbolAddress((void**)&gt,  g_t);
    cudaGetSymbolAddress((void**)&gwp, g_wp);

    cudaFuncSetAttribute(conv_mma<0>, cudaFuncAttributeMaxDynamicSharedMemorySize, SMEM_DYN);
    cudaFuncSetAttribute(conv_mma<1>, cudaFuncAttributeMaxDynamicSharedMemorySize, SMEM_DYN);
    cudaFuncSetAttribute(conv_mma<2>, cudaFuncAttributeMaxDynamicSharedMemorySize, SMEM_DYN);

    pack_w<<<(2*128*128*9 + 255)/256, 256>>>(w1, w2, gwp);
    round_x<<<4096, 256>>>((const float4*)x, (float4*)gxr, (int)((size_t)BATCH*CH*HGT*WID/4));

    const float* wp1 = gwp;
    const float* wp2 = gwp + 147456;
    dim3 grid(HGT, BATCH);

    conv_mma<0><<<grid, NTHR, SMEM_DYN>>>(gxr, wp1, b1, nullptr, gt,  nullptr);
    conv_mma<1><<<grid, NTHR, SMEM_DYN>>>(gt,  wp2, b2, x,       gx,  gxr);
    conv_mma<0><<<grid, NTHR, SMEM_DYN>>>(gxr, wp1, b1, nullptr, gt,  nullptr);
    conv_mma<1><<<grid, NTHR, SMEM_DYN>>>(gt,  wp2, b2, gx,      gx,  gxr);
    conv_mma<0><<<grid, NTHR, SMEM_DYN>>>(gxr, wp1, b1, nullptr, gt,  nullptr);
    conv_mma<2><<<grid, NTHR, SMEM_DYN>>>(gt,  wp2, b2, gx,      out, nullptr);
}

// round 5
// speedup vs baseline: 4.5546x; 1.2144x over previous
#include <cuda_runtime.h>
#include <cstdint>

#define BATCH 16
#define CH    128
#define HGT   128
#define WID   128
#define NTHR  256

#define NSTAGE 24            // 3 kh * 8 ci-chunks (16 ci each)
#define A_F    3072          // floats of A per stage (fragment-packed)
#define B_CI_STRIDE 280      // floats per ci (2 rows of 136 + 8 pad)
#define B_ROW_OFF   136
#define SLOT_F 7552          // 3072 + 16*280
#define SMEM_DYN (2*SLOT_F*4)   // 60416 B -> 2 CTAs/SM

__device__ float g_x [(size_t)BATCH*CH*HGT*WID];
__device__ float g_xr[(size_t)BATCH*CH*HGT*WID];
__device__ float g_t [(size_t)BATCH*CH*HGT*WID];
__device__ float g_wp[2*2*24*3072];   // [set][cohalf][stage][fragment-packed 3072]

// ---------- helpers ----------
__device__ __forceinline__ uint32_t smem_u32(const void* p){
    uint32_t a; asm("{ .reg .u64 t; cvta.to.shared.u64 t, %1; cvt.u32.u64 %0, t; }":"=r"(a):"l"(p));
    return a;
}
__device__ __forceinline__ float f2tf32(float f){
    uint32_t r; asm("cvt.rna.tf32.f32 %0, %1;":"=r"(r):"f"(f));
    return __uint_as_float(r);
}
__device__ __forceinline__ void cp16(uint32_t dst, const void* src, uint32_t ss){
    asm volatile("cp.async.cg.shared.global [%0], [%1], 16, %2;"
                 :: "r"(dst), "l"(src), "r"(ss) : "memory");
}
#define CP_COMMIT() asm volatile("cp.async.commit_group;":::"memory")
template<int N> __device__ __forceinline__ void cp_wait(){
    asm volatile("cp.async.wait_group %0;"::"n"(N):"memory");
}
__device__ __forceinline__ void mma8(float* d, const uint32_t* a, uint32_t b0, uint32_t b1){
    asm volatile("mma.sync.aligned.m16n8k8.row.col.f32.tf32.tf32.f32 "
        "{%0,%1,%2,%3}, {%4,%5,%6,%7}, {%8,%9}, {%0,%1,%2,%3};"
        : "+f"(d[0]), "+f"(d[1]), "+f"(d[2]), "+f"(d[3])
        : "r"(a[0]), "r"(a[1]), "r"(a[2]), "r"(a[3]), "r"(b0), "r"(b1));
}

// ---------- weight pack: per-lane MMA fragment layout ----------
// dst[((((set*2+ch)*24+s)*3+kw)*2+k8)*4+m16][lane][j] ; j=0..3 = a0..a3 of m16n8k8
__global__ void pack_w(const float* __restrict__ w1, const float* __restrict__ w2,
                       float* __restrict__ dst){
    int idx = blockIdx.x*blockDim.x + threadIdx.x;
    if (idx >= 2*147456) return;
    int r = idx;
    int set = r / 147456; r %= 147456;
    int ch  = r / 73728;  r %= 73728;
    int s   = r / 3072;   r %= 3072;
    int kw  = r / 1024;   r %= 1024;
    int k8  = r / 512;    r %= 512;
    int m16 = r / 128;    r %= 128;
    int lane= r >> 2;
    int j   = r & 3;
    int g = lane>>2, t = lane&3;
    int co   = ch*64 + m16*16 + g + ((j&1)<<3);
    int kcol = t + ((j>>1)<<2);
    int kh = s>>3, chunk = s&7;
    int ci = chunk*16 + k8*8 + kcol;
    const float* w = set ? w2 : w1;
    dst[idx] = f2tf32(w[(size_t)co*(CH*9) + ci*9 + kh*3 + kw]);
}

// ---------- round pre-pass ----------
__global__ void round_x(const float4* __restrict__ in, float4* __restrict__ out, int n4){
    for (int i = blockIdx.x*blockDim.x + threadIdx.x; i < n4; i += gridDim.x*blockDim.x){
        float4 v = in[i];
        v.x = f2tf32(v.x); v.y = f2tf32(v.y); v.z = f2tf32(v.z); v.w = f2tf32(v.w);
        out[i] = v;
    }
}

// ---------- conv kernel ----------
// MODE 0: out = rna(relu(conv+b))
// MODE 1: v = xadd + (conv+b)/3 ; out = v ; out2 = rna(v)
// MODE 2: out = relu(xadd + (conv+b)/3)
template<int MODE>
__global__ void __launch_bounds__(NTHR, 2)
conv_mma(const float* __restrict__ in, const float* __restrict__ wp,
         const float* __restrict__ bias, const float* __restrict__ xadd,
         float* __restrict__ out, float* __restrict__ out2)
{
    extern __shared__ __align__(1024) float sm[];
    const int tid = threadIdx.x, lane = tid&31, wid = tid>>5;
    const int g = lane>>2, t = lane&3;
    const int wm = wid&1, wn = wid>>1;        // wm: m-half of 64co ; wn: 0..3
    const int brow = wn>>1, nb = (wn&1)*64;   // output row sel + px base
    const int h0 = blockIdx.x*2, b = blockIdx.y, ch = blockIdx.z;
    const float* in_b = in + (size_t)b*CH*HGT*WID;
    const float* wpc  = wp + (size_t)ch*73728;

    float d[2][8][4];
#pragma unroll
    for (int mt=0;mt<2;mt++)
#pragma unroll
        for (int nt=0;nt<8;nt++)
#pragma unroll
            for (int c=0;c<4;c++) d[mt][nt][c] = 0.f;

    auto issue_stage = [&](int s, int slot){
        float* sl = sm + slot*SLOT_F;
        uint32_t base = smem_u32(sl);
        // A: fragment-packed, contiguous copy (12288 B = 768 cp16)
        const float4* asrc = (const float4*)(wpc + (size_t)s*A_F);
#pragma unroll
        for (int i=0;i<3;i++){
            int u = tid + i*256;
            cp16(base + u*16, asrc + u, 16);
        }
        // B: 16 ci x 2 rows x 128 floats = 1024 cp16 (4 per thread)
        const int kh = s>>3, chunk = s&7;
#pragma unroll
        for (int i=0;i<4;i++){
            int v = tid + i*256;
            int ci = v>>6, rem = v&63, row = rem>>5, cw = rem&31;
            int r = h0 + kh - 1 + row;
            uint32_t ss = ((unsigned)r < HGT) ? 16u : 0u;
            int rc = ((unsigned)r < HGT) ? r : 0;
            const float* src = in_b + ((size_t)(chunk*16+ci)*HGT + rc)*WID + cw*4;
            cp16(base + A_F*4 + ci*1120 + row*544 + 16 + cw*16, src, ss);
        }
        // halo edge floats (w=-1 at float idx 3, w=128 at idx 132): always zero
        if (tid < 64){
            int ci = tid>>2, rem = tid&3, row = rem>>1;
            sl[A_F + ci*B_CI_STRIDE + row*B_ROW_OFF + ((rem&1)?132:3)] = 0.f;
        }
    };

    issue_stage(0, 0);
    CP_COMMIT();

    for (int s=0; s<NSTAGE; s++){
        if (s < NSTAGE-1){ issue_stage(s+1, (s+1)&1); CP_COMMIT(); cp_wait<1>(); }
        else             { cp_wait<0>(); }
        __syncthreads();

        const float* A  = sm + (s&1)*SLOT_F;
        const float* Bb = A + A_F;
#pragma unroll
        for (int kw=0; kw<3; kw++){
#pragma unroll
            for (int k8=0; k8<2; k8++){
                const int col = k8*8 + t;
                float4 av[2];
#pragma unroll
                for (int mt=0; mt<2; mt++)
                    av[mt] = *(const float4*)(A + ((kw*2+k8)*4 + wm*2+mt)*128 + lane*4);
                const float* bp = Bb + col*B_CI_STRIDE + brow*B_ROW_OFF + 3 + nb + g + kw;
#pragma unroll
                for (int nt=0; nt<8; nt++){
                    uint32_t b0 = __float_as_uint(bp[nt*8]);
                    uint32_t b1 = __float_as_uint(bp[nt*8 + 4*B_CI_STRIDE]);
                    mma8(d[0][nt], (const uint32_t*)&av[0], b0, b1);
                    mma8(d[1][nt], (const uint32_t*)&av[1], b0, b1);
                }
            }
        }
        __syncthreads();
    }

    // ---- epilogue ----
    const float inv3 = 1.0f/3.0f;
    const int h = h0 + brow;
#pragma unroll
    for (int mt=0; mt<2; mt++){
        const int co0 = ch*64 + wm*32 + mt*16 + g;
        const int co1 = co0 + 8;
        const float bv0 = bias[co0], bv1 = bias[co1];
        float* o0 = out + (((size_t)b*CH + co0)*HGT + h)*WID;
        float* o1 = out + (((size_t)b*CH + co1)*HGT + h)*WID;
        const float* x0 = (MODE!=0) ? xadd + (((size_t)b*CH + co0)*HGT + h)*WID : nullptr;
        const float* x1 = (MODE!=0) ? xadd + (((size_t)b*CH + co1)*HGT + h)*WID : nullptr;
        float* r0 = (MODE==1) ? out2 + (((size_t)b*CH + co0)*HGT + h)*WID : nullptr;
        float* r1 = (MODE==1) ? out2 + (((size_t)b*CH + co1)*HGT + h)*WID : nullptr;
#pragma unroll
        for (int nt=0; nt<8; nt++){
            const int n = nb + nt*8 + t*2;
            float v00 = d[mt][nt][0] + bv0, v01 = d[mt][nt][1] + bv0;
            float v10 = d[mt][nt][2] + bv1, v11 = d[mt][nt][3] + bv1;
            if (MODE == 0){
                v00 = f2tf32(fmaxf(v00, 0.f)); v01 = f2tf32(fmaxf(v01, 0.f));
                v10 = f2tf32(fmaxf(v10, 0.f)); v11 = f2tf32(fmaxf(v11, 0.f));
                *(float2*)(o0 + n) = make_float2(v00, v01);
                *(float2*)(o1 + n) = make_float2(v10, v11);
            } else {
                float2 xa = *(const float2*)(x0 + n);
                float2 xb = *(const float2*)(x1 + n);
                v00 = xa.x + inv3*v00; v01 = xa.y + inv3*v01;
                v10 = xb.x + inv3*v10; v11 = xb.y + inv3*v11;
                if (MODE == 2){
                    v00 = fmaxf(v00,0.f); v01 = fmaxf(v01,0.f);
                    v10 = fmaxf(v10,0.f); v11 = fmaxf(v11,0.f);
                }
                *(float2*)(o0 + n) = make_float2(v00, v01);
                *(float2*)(o1 + n) = make_float2(v10, v11);
                if (MODE == 1){
                    *(float2*)(r0 + n) = make_float2(f2tf32(v00), f2tf32(v01));
                    *(float2*)(r1 + n) = make_float2(f2tf32(v10), f2tf32(v11));
                }
            }
        }
    }
}

// ---------- launch ----------
extern "C" void kernel_launch(void* const* d_in, const int* in_sizes, int n_in,
                              void* d_out, int out_size)
{
    const float* x  = (const float*)d_in[0];
    const float* w1 = (const float*)d_in[1];
    const float* b1 = (const float*)d_in[2];
    const float* w2 = (const float*)d_in[3];
    const float* b2 = (const float*)d_in[4];
    float* out = (float*)d_out;

    float *gx, *gxr, *gt, *gwp;
    cudaGetSymbolAddress((void**)&gx,  g_x);
    cudaGetSymbolAddress((void**)&gxr, g_xr);
    cudaGetSymbolAddress((void**)&gt,  g_t);
    cudaGetSymbolAddress((void**)&gwp, g_wp);

    cudaFuncSetAttribute(conv_mma<0>, cudaFuncAttributeMaxDynamicSharedMemorySize, SMEM_DYN);
    cudaFuncSetAttribute(conv_mma<1>, cudaFuncAttributeMaxDynamicSharedMemorySize, SMEM_DYN);
    cudaFuncSetAttribute(conv_mma<2>, cudaFuncAttributeMaxDynamicSharedMemorySize, SMEM_DYN);

    pack_w<<<(2*147456 + 255)/256, 256>>>(w1, w2, gwp);
    round_x<<<4096, 256>>>((const float4*)x, (float4*)gxr, (int)((size_t)BATCH*CH*HGT*WID/4));

    const float* wp1 = gwp;
    const float* wp2 = gwp + 147456;
    dim3 grid(HGT/2, BATCH, 2);

    conv_mma<0><<<grid, NTHR, SMEM_DYN>>>(gxr, wp1, b1, nullptr, gt,  nullptr);
    conv_mma<1><<<grid, NTHR, SMEM_DYN>>>(gt,  wp2, b2, x,       gx,  gxr);
    conv_mma<0><<<grid, NTHR, SMEM_DYN>>>(gxr, wp1, b1, nullptr, gt,  nullptr);
    conv_mma<1><<<grid, NTHR, SMEM_DYN>>>(gt,  wp2, b2, gx,      gx,  gxr);
    conv_mma<0><<<grid, NTHR, SMEM_DYN>>>(gxr, wp1, b1, nullptr, gt,  nullptr);
    conv_mma<2><<<grid, NTHR, SMEM_DYN>>>(gt,  wp2, b2, gx,      out, nullptr);
}